// round 14
// baseline (speedup 1.0000x reference)
#include <cuda_runtime.h>
#include <cuda_fp16.h>
#include <cstdint>

#define NH 256
#define NL 4096
#define PHH 72     // Uh/CH pitch in halves (144B rows, 16B-aligned for ldmatrix)
#define EPH 68     // E1h/IjH pitch in halves (136B rows, 8B-aligned for LDS.64)
#define IP32 66    // Inj32 pitch in floats (8 rows only)
#define UH_OFF  0
#define IJH_OFF 18432
#define E1_OFF  27136
#define CH_OFF  35840
#define SMEMF   54272      // CH 18432 at end; Inj32(2112)+R8S(2048) overlay CH region

static __device__ __forceinline__ uint32_t s2u(const void* p) {
    uint32_t a;
    asm("{ .reg .u64 t; cvta.to.shared.u64 t, %1; cvt.u32.u64 %0, t; }" : "=r"(a) : "l"(p));
    return a;
}
static __device__ __forceinline__ void ldmA(uint32_t* a, uint32_t addr) {
    asm volatile("ldmatrix.sync.aligned.m8n8.x4.shared.b16 {%0,%1,%2,%3}, [%4];"
                 : "=r"(a[0]), "=r"(a[1]), "=r"(a[2]), "=r"(a[3]) : "r"(addr));
}
static __device__ __forceinline__ void mma16(float* c, const uint32_t* a,
                                             uint32_t b0, uint32_t b1) {
    asm volatile(
        "mma.sync.aligned.m16n8k16.row.col.f32.f16.f16.f32 "
        "{%0,%1,%2,%3},{%4,%5,%6,%7},{%8,%9},{%0,%1,%2,%3};"
        : "+f"(c[0]), "+f"(c[1]), "+f"(c[2]), "+f"(c[3])
        : "r"(a[0]), "r"(a[1]), "r"(a[2]), "r"(a[3]), "r"(b0), "r"(b1));
}
static __device__ __forceinline__ float2 cmad(float2 m, float2 c, float2 p) {
    float2 r;
    r.x = fmaf(m.x, c.x, fmaf(-m.y, c.y, p.x));
    r.y = fmaf(m.x, c.y, fmaf( m.y, c.x, p.y));
    return r;
}
static __device__ __forceinline__ uint32_t packh2(float a, float b) {
    __half2 h = __floats2half2_rn(a, b);
    return *(uint32_t*)&h;
}
// pair-permute within 16-half k-groups so B-frag (k-pair p, p+4) is one LDS.64
static __device__ __forceinline__ int perm16(int m) {
    int p = (m >> 1) & 7;
    int np = ((p & 3) << 1) | (p >> 2);
    return (m & ~15) | (np << 1) | (m & 1);
}

// ---------------------------------------------------------------------------
// Single-tile fused kernel. CTA = (h, b-pair), M=128, 256 threads, grid 1024.
// (256,3): 84-reg cap -> no spill (the 64-reg/(256,4) config spills; RF caps
// residency at 4 CTAs anyway, so 3 CTAs + clean code is the other optimum).
// Dyn SMEM: Uh[128][72]h | IjH[64][68]h | E1h[64][68]h | CH[128][72]h
//           (Inj32[8][66]f + R8S[8][32]f2 overlay CH during table build)
// ---------------------------------------------------------------------------
__global__ __launch_bounds__(256, 3) void k_fused(
        const float* __restrict__ u,     const float* __restrict__ theta,
        const float* __restrict__ av_,   const float* __restrict__ Dp,
        const float* __restrict__ b_p,   const float* __restrict__ c_p,
        const float* __restrict__ x0,    float* __restrict__ out) {
    extern __shared__ char smc[];
    __half* Uh    = (__half*)(smc + UH_OFF);
    __half* IjH   = (__half*)(smc + IJH_OFF);
    __half* E1h   = (__half*)(smc + E1_OFF);
    __half* CH    = (__half*)(smc + CH_OFF);
    float*  Inj32 = (float*)(smc + CH_OFF);          // overlay (rows 0..7)
    float2* R8S   = (float2*)(smc + CH_OFF + 2112);  // overlay, [8][32]
    __shared__ float2 swS[32];
    __shared__ float2 c0S[32];
    __shared__ float2 r64S[32];
    __shared__ uint32_t Gt32[128];      // half2(f[t], f[t-1]), t = 2q + p - 64
    __shared__ float2 Sbuf[4][64];

    int tid  = threadIdx.x;
    int lane = tid & 31, warp = tid >> 5;
    int mw = warp & 3, nw = warp >> 2;          // 4(M) x 2(N) warp grid
    int h = blockIdx.x >> 2, b0 = (blockIdx.x & 3) * 2;
    const float T = 1.0f / (float)(NL - 1);
    float Dv = __ldg(&Dp[h]);
    uint32_t sb = s2u(smc);

    if (tid < 128) Gt32[tid] = 0u;              // zero-pad (ordered by later syncs)

    // ---- phase 0: u load + fp16 convert ----
    #pragma unroll
    for (int it = 0; it < 8; it++) {
        int idx = it * 256 + tid;
        int row = idx >> 4, c4 = (idx & 15) << 2;
        const float* src = u + ((size_t)((b0 + (row >> 6)) * NH + h)) * NL
                             + (row & 63) * 64 + c4;
        float4 v = *(const float4*)src;
        uint2 pk;
        pk.x = packh2(v.x, v.y);
        pk.y = packh2(v.z, v.w);
        *(uint2*)(Uh + row * PHH + c4) = pk;
    }

    // ---- phase A: params + short chains (warp 0 only; MUFU transcendentals) ----
    if (tid < 32) {
        int d = tid, idx = h * 32 + d;
        float av = fabsf(av_[idx]);
        float th = theta[idx];
        float er = __expf(-av * T);
        float sn, cn;
        __sincosf(th * T, &sn, &cn);
        float rr = er * cn, ri = er * sn;
        float den = av * av + th * th;
        float nr = rr - 1.0f, ni = ri;
        float t0r = (nr * -av + ni * th) / den;
        float t0i = (ni * -av - nr * th) / den;
        float q = b_p[idx] * c_p[idx];
        swS[d] = make_float2(2.0f * t0r * q, 2.0f * t0i * q);
        float g = 4.0f * T * c_p[idx] * x0[idx];
        float rm2 = rr * rr + ri * ri;
        c0S[d] = make_float2(g * rr / rm2, -g * ri / rm2);
        // r^1..r^8 (fp32) into Inj32 rows 0..7
        float pr = rr, pi = ri;
        Inj32[2 * d] = pr; Inj32[2 * d + 1] = pi;
        #pragma unroll
        for (int p = 2; p <= 8; p++) {
            float npr = fmaf(pr, rr, -pi * ri);
            float npi = fmaf(pr, ri,  pi * rr);
            pr = npr; pi = npi;
            Inj32[(p - 1) * IP32 + 2 * d]     = pr;
            Inj32[(p - 1) * IP32 + 2 * d + 1] = pi;
        }
        // (r^8)^k, k=1..8
        float qr = pr, qi = pi;
        R8S[0 * 32 + d] = make_float2(qr, qi);
        #pragma unroll
        for (int k = 2; k <= 8; k++) {
            float nqr = fmaf(qr, pr, -qi * pi);
            float nqi = fmaf(qr, pi,  qi * pr);
            qr = nqr; qi = nqi;
            R8S[(k - 1) * 32 + d] = make_float2(qr, qi);
        }
        r64S[d] = make_float2(qr, qi);           // r^64
    }
    __syncthreads();

    // ---- fused table sweep: IjH + E1h (both perm16-packed) ----
    {
        int d = tid & 31;
        int i0 = tid >> 5;                       // i = i0 + 8*it
        float2 w = swS[d];
        int ip = d & 7;
        int np = ((ip & 3) << 1) | (ip >> 2);
        int colb = ((2 * d) & ~15) + 2 * np;     // IjH packed col (invariant)
        #pragma unroll
        for (int it = 0; it < 8; it++) {
            int i = i0 + it * 8;
            float re, im;                        // r^{i+1}
            if (i < 8) {
                re = Inj32[i * IP32 + 2 * d];
                im = Inj32[i * IP32 + 2 * d + 1];
            } else {
                int v = i + 1;                   // 9..64
                int k = (v - 1) >> 3, j = v - (k << 3);
                float2 A = R8S[(k - 1) * 32 + d];
                float bRe = Inj32[(j - 1) * IP32 + 2 * d];
                float bIm = Inj32[(j - 1) * IP32 + 2 * d + 1];
                re = fmaf(A.x, bRe, -A.y * bIm);
                im = fmaf(A.x, bIm,  A.y * bRe);
            }
            *(uint32_t*)(IjH + i * EPH + colb) = packh2(re, -im);
            if (i < 63) {
                int col = perm16(62 - i);
                E1h[(2 * d) * EPH + col]     = __float2half_rn(fmaf(w.x, re, -w.y * im));
                E1h[(2 * d + 1) * EPH + col] = __float2half_rn(fmaf(w.x, im,  w.y * re));
            } else {
                int col = perm16(63);            // m=63 -> r^0 = 1
                E1h[(2 * d) * EPH + col]     = __float2half_rn(w.x);
                E1h[(2 * d + 1) * EPH + col] = __float2half_rn(w.y);
            }
        }
    }
    __syncthreads();

    // ---- f[j] from IjH -> Gt direct (4 threads per j, shfl reduce) ----
    {
        int j = tid >> 2, dg = tid & 3;
        float s = 0.0f;
        #pragma unroll
        for (int dd = 0; dd < 8; dd++) {
            int d = dg * 8 + dd;
            float2 w = swS[d];
            float ijE, ijO;                      // (Re r^j, -Im r^j)
            if (j == 0) { ijE = 1.0f; ijO = 0.0f; }
            else {
                int ip = d & 7;
                int np = ((ip & 3) << 1) | (ip >> 2);
                int colb = ((2 * d) & ~15) + 2 * np;
                ijE = __half2float(IjH[(j - 1) * EPH + colb]);
                ijO = __half2float(IjH[(j - 1) * EPH + colb + 1]);
            }
            s = fmaf(w.x, ijE, fmaf(w.y, ijO, s));
        }
        s += __shfl_xor_sync(0xFFFFFFFFu, s, 1);
        s += __shfl_xor_sync(0xFFFFFFFFu, s, 2);
        if (dg == 0) {
            __half* Gt2 = (__half*)Gt32;
            __half hs = __float2half_rn(s);
            int p0 = j & 1, q0 = (j + 64 - p0) >> 1;   // f0 slot: t = j
            Gt2[(p0 * 64 + q0) * 2] = hs;
            if (j < 63) {                               // f1 slot: t = j+1
                int tt = j + 1;
                int p1 = tt & 1, q1 = (tt + 64 - p1) >> 1;
                Gt2[(p1 * 64 + q1) * 2 + 1] = hs;
            }
        }
    }

    int bn8 = lane >> 2, bl3 = lane & 3;
    uint32_t aoff = (uint32_t)(mw * 32 + (lane & 7) + ((lane >> 3) & 1) * 8)
                    * (PHH * 2) + ((lane >> 4) & 1) * 16;

    // ---- P GEMM: P[row][dt] = sum_m U[row][m] * E1[dt][m], K=64 ----
    {
        float pc[2][4][4];
        #pragma unroll
        for (int mt = 0; mt < 2; mt++)
            #pragma unroll
            for (int j = 0; j < 4; j++)
                #pragma unroll
                for (int q = 0; q < 4; q++) pc[mt][j][q] = 0.0f;

        #pragma unroll
        for (int ks = 0; ks < 4; ks++) {
            uint32_t a[2][4];
            ldmA(a[0], sb + UH_OFF + aoff + ks * 32);
            ldmA(a[1], sb + UH_OFF + aoff + 16 * (PHH * 2) + ks * 32);
            #pragma unroll
            for (int j = 0; j < 4; j++) {
                int tn = 2 * j + nw;
                uint2 bb = *(const uint2*)
                    (E1h + (tn * 8 + bn8) * EPH + ks * 16 + 4 * bl3);
                mma16(pc[0][j], a[0], bb.x, bb.y);
                mma16(pc[1][j], a[1], bb.x, bb.y);
            }
        }
        __syncthreads();   // CH overlay (Inj32/R8S) reads done -> CH writes safe
        #pragma unroll
        for (int mt = 0; mt < 2; mt++)
            #pragma unroll
            for (int j = 0; j < 4; j++) {
                int tn = 2 * j + nw;
                int ra  = mw * 32 + mt * 16 + bn8;
                int col = tn * 8 + 2 * bl3;
                *(uint32_t*)(CH + ra * PHH + col)       = packh2(pc[mt][j][0], pc[mt][j][1]);
                *(uint32_t*)(CH + (ra + 8) * PHH + col) = packh2(pc[mt][j][2], pc[mt][j][3]);
            }
    }
    __syncthreads();

    // ---- carry scan in CH ----
    {
        int tt = tid >> 6, seq = tid & 63;
        int bl = seq >> 5, d = seq & 31;
        float2 rl = r64S[d];
        float2 R = rl;                           // rl^16
        #pragma unroll
        for (int sq = 0; sq < 4; sq++) {
            float2 nR;
            nR.x = fmaf(R.x, R.x, -R.y * R.y);
            nR.y = 2.0f * R.x * R.y;
            R = nR;
        }
        __half* bp = CH + (bl * 64 + tt * 16) * PHH + 2 * d;
        float2 s = make_float2(0.0f, 0.0f);
        #pragma unroll
        for (int i = 0; i < 16; i++)
            s = cmad(rl, s, __half22float2(*(__half2*)(bp + i * PHH)));
        Sbuf[tt][seq] = s;
        __syncthreads();
        float2 X = c0S[d];
        for (int k = 0; k < tt; k++)             // tt uniform per warp
            X = cmad(R, X, Sbuf[k][seq]);
        #pragma unroll
        for (int i = 0; i < 16; i++) {
            float2 pv = __half22float2(*(__half2*)(bp + i * PHH));
            *(__half2*)(bp + i * PHH) = __floats2half2_rn(X.x, X.y);
            X = cmad(rl, X, pv);
        }
    }
    __syncthreads();

    // ---- Y GEMM ----
    float yc[2][4][4];
    #pragma unroll
    for (int mt = 0; mt < 2; mt++)
        #pragma unroll
        for (int j = 0; j < 4; j++)
            #pragma unroll
            for (int q = 0; q < 4; q++) yc[mt][j][q] = 0.0f;

    // half 2: u x Toeplitz(f), triangle-skip
    #pragma unroll
    for (int ks = 0; ks < 4; ks++) {
        uint32_t a[2][4];
        ldmA(a[0], sb + UH_OFF + aoff + ks * 32);
        ldmA(a[1], sb + UH_OFF + aoff + 16 * (PHH * 2) + ks * 32);
        #pragma unroll
        for (int j = 0; j < 4; j++) {
            int tn = 2 * j + nw;
            if (tn * 8 + 7 >= ks * 16) {
                int t0 = tn * 8 + bn8 - ks * 16 - 2 * bl3;
                int p  = t0 & 1;
                int q0 = (t0 + 64) >> 1;
                uint32_t b0 = Gt32[p * 64 + q0];
                uint32_t b1 = Gt32[p * 64 + q0 - 4];
                mma16(yc[0][j], a[0], b0, b1);
                mma16(yc[1][j], a[1], b0, b1);
            }
        }
    }
    // half 1: carries x injection
    #pragma unroll
    for (int ks = 0; ks < 4; ks++) {
        uint32_t a[2][4];
        ldmA(a[0], sb + CH_OFF + aoff + ks * 32);
        ldmA(a[1], sb + CH_OFF + aoff + 16 * (PHH * 2) + ks * 32);
        #pragma unroll
        for (int j = 0; j < 4; j++) {
            int tn = 2 * j + nw;
            uint2 bb = *(const uint2*)
                (IjH + (tn * 8 + bn8) * EPH + ks * 16 + 4 * bl3);
            mma16(yc[0][j], a[0], bb.x, bb.y);
            mma16(yc[1][j], a[1], bb.x, bb.y);
        }
    }

    // ---- epilogue: y = Y + D*u (u re-read from global, exact fp32) ----
    #pragma unroll
    for (int mt = 0; mt < 2; mt++)
        #pragma unroll
        for (int half = 0; half < 2; half++) {
            int r = mw * 32 + mt * 16 + bn8 + half * 8;
            size_t base = ((size_t)((b0 + (r >> 6)) * NH + h)) * NL + (r & 63) * 64;
            const float* up = u + base;
            float* op = out + base;
            #pragma unroll
            for (int j = 0; j < 4; j++) {
                int col = (2 * j + nw) * 8 + 2 * bl3;
                float2 uv = *(const float2*)(up + col);
                float2 o2;
                o2.x = fmaf(Dv, uv.x, yc[mt][j][half * 2 + 0]);
                o2.y = fmaf(Dv, uv.y, yc[mt][j][half * 2 + 1]);
                *(float2*)(op + col) = o2;
            }
        }
}

// ---------------------------------------------------------------------------
extern "C" void kernel_launch(void* const* d_in, const int* in_sizes, int n_in,
                              void* d_out, int out_size) {
    (void)in_sizes; (void)n_in; (void)out_size;
    const float* u     = (const float*)d_in[0];
    const float* theta = (const float*)d_in[1];
    const float* a     = (const float*)d_in[2];
    const float* Dp    = (const float*)d_in[3];
    const float* b_p   = (const float*)d_in[4];
    const float* c_p   = (const float*)d_in[5];
    const float* x0    = (const float*)d_in[6];
    float* out = (float*)d_out;

    cudaFuncSetAttribute(k_fused, cudaFuncAttributeMaxDynamicSharedMemorySize, SMEMF);
    k_fused<<<1024, 256, SMEMF>>>(u, theta, a, Dp, b_p, c_p, x0, out);
}

// round 15
// speedup vs baseline: 1.0073x; 1.0073x over previous
#include <cuda_runtime.h>
#include <cuda_fp16.h>
#include <cstdint>

#define NH 256
#define NL 4096
#define PHH 72     // Uh/CH pitch in halves (144B rows, 16B-aligned for ldmatrix)
#define EPH 68     // E1h/IjH pitch in halves (136B rows, 8B-aligned for LDS.64)
#define IP32 66    // Inj32 pitch in floats (8 rows only)
#define UH_OFF  0
#define IJH_OFF 18432
#define E1_OFF  27136
#define CH_OFF  35840
#define SMEMF   54272      // CH 18432 at end; Inj32(2112)+R8S(2048) overlay CH region

static __device__ __forceinline__ uint32_t s2u(const void* p) {
    uint32_t a;
    asm("{ .reg .u64 t; cvta.to.shared.u64 t, %1; cvt.u32.u64 %0, t; }" : "=r"(a) : "l"(p));
    return a;
}
static __device__ __forceinline__ void ldmA(uint32_t* a, uint32_t addr) {
    asm volatile("ldmatrix.sync.aligned.m8n8.x4.shared.b16 {%0,%1,%2,%3}, [%4];"
                 : "=r"(a[0]), "=r"(a[1]), "=r"(a[2]), "=r"(a[3]) : "r"(addr));
}
static __device__ __forceinline__ void mma16(float* c, const uint32_t* a,
                                             uint32_t b0, uint32_t b1) {
    asm volatile(
        "mma.sync.aligned.m16n8k16.row.col.f32.f16.f16.f32 "
        "{%0,%1,%2,%3},{%4,%5,%6,%7},{%8,%9},{%0,%1,%2,%3};"
        : "+f"(c[0]), "+f"(c[1]), "+f"(c[2]), "+f"(c[3])
        : "r"(a[0]), "r"(a[1]), "r"(a[2]), "r"(a[3]), "r"(b0), "r"(b1));
}
static __device__ __forceinline__ float2 cmad(float2 m, float2 c, float2 p) {
    float2 r;
    r.x = fmaf(m.x, c.x, fmaf(-m.y, c.y, p.x));
    r.y = fmaf(m.x, c.y, fmaf( m.y, c.x, p.y));
    return r;
}
static __device__ __forceinline__ uint32_t packh2(float a, float b) {
    __half2 h = __floats2half2_rn(a, b);
    return *(uint32_t*)&h;
}
// pair-permute within 16-half k-groups so B-frag (k-pair p, p+4) is one LDS.64
static __device__ __forceinline__ int perm16(int m) {
    int p = (m >> 1) & 7;
    int np = ((p & 3) << 1) | (p >> 2);
    return (m & ~15) | (np << 1) | (m & 1);
}

// ---------------------------------------------------------------------------
// Single-tile fused kernel. CTA = (h, b-pair), M=128, 256 threads, grid 1024.
// Dyn SMEM: Uh[128][72]h | IjH[64][68]h | E1h[64][68]h | CH[128][72]h
//           (Inj32[8][66]f + R8S[8][32]f2 overlay CH during table build)
// ---------------------------------------------------------------------------
__global__ __launch_bounds__(256, 3) void k_fused(
        const float* __restrict__ u,     const float* __restrict__ theta,
        const float* __restrict__ av_,   const float* __restrict__ Dp,
        const float* __restrict__ b_p,   const float* __restrict__ c_p,
        const float* __restrict__ x0,    float* __restrict__ out) {
    extern __shared__ char smc[];
    __half* Uh    = (__half*)(smc + UH_OFF);
    __half* IjH   = (__half*)(smc + IJH_OFF);
    __half* E1h   = (__half*)(smc + E1_OFF);
    __half* CH    = (__half*)(smc + CH_OFF);
    float*  Inj32 = (float*)(smc + CH_OFF);          // overlay (rows 0..7)
    float2* R8S   = (float2*)(smc + CH_OFF + 2112);  // overlay, [8][32]
    __shared__ float2 swS[32];
    __shared__ float2 c0S[32];
    __shared__ float2 r64S[32];
    __shared__ uint32_t Gt32[128];      // half2(f[t], f[t-1]), t = 2q + p - 64
    __shared__ float2 Sbuf[4][64];

    int tid  = threadIdx.x;
    int lane = tid & 31, warp = tid >> 5;
    int mw = warp & 3, nw = warp >> 2;          // 4(M) x 2(N) warp grid
    int h = blockIdx.x >> 2, b0 = (blockIdx.x & 3) * 2;
    const float T = 1.0f / (float)(NL - 1);
    float Dv = __ldg(&Dp[h]);
    uint32_t sb = s2u(smc);

    if (tid < 128) Gt32[tid] = 0u;              // zero-pad (ordered by later syncs)

    // ---- phase 0: u load + fp16 convert ----
    #pragma unroll
    for (int it = 0; it < 8; it++) {
        int idx = it * 256 + tid;
        int row = idx >> 4, c4 = (idx & 15) << 2;
        const float* src = u + ((size_t)((b0 + (row >> 6)) * NH + h)) * NL
                             + (row & 63) * 64 + c4;
        float4 v = *(const float4*)src;
        uint2 pk;
        pk.x = packh2(v.x, v.y);
        pk.y = packh2(v.z, v.w);
        *(uint2*)(Uh + row * PHH + c4) = pk;
    }

    // ---- phase A pass 1: r^p for p=1..8 (256 threads, MUFU), warp 0 sw/c0 ----
    {
        int p = (tid >> 5) + 1;                  // 1..8
        int d = tid & 31;
        int idx = h * 32 + d;
        float av = fabsf(av_[idx]);
        float th = theta[idx];
        float er = __expf(-av * T * (float)p);
        float sn, cn;
        __sincosf(th * T * (float)p, &sn, &cn);
        float rr = er * cn, ri = er * sn;
        Inj32[(p - 1) * IP32 + 2 * d]     = rr;
        Inj32[(p - 1) * IP32 + 2 * d + 1] = ri;
        if (p == 1) {                            // warp 0: uses own rr/ri = r^1
            float den = av * av + th * th;
            float nr = rr - 1.0f, ni = ri;
            float t0r = (nr * -av + ni * th) / den;
            float t0i = (ni * -av - nr * th) / den;
            float q = b_p[idx] * c_p[idx];
            swS[d] = make_float2(2.0f * t0r * q, 2.0f * t0i * q);
            float g = 4.0f * T * c_p[idx] * x0[idx];
            float rm2 = rr * rr + ri * ri;
            c0S[d] = make_float2(g * rr / rm2, -g * ri / rm2);
        }
    }
    __syncthreads();

    // ---- phase A pass 2: R8S[k-1][d] = (r^8)^k, k=1..8 (<=7 predicated cmuls) ----
    {
        int k = (tid >> 5) + 1;
        int d = tid & 31;
        float2 r8 = *(float2*)&Inj32[7 * IP32 + 2 * d];
        float2 v = r8;
        #pragma unroll
        for (int kk = 1; kk < 8; kk++)
            if (kk < k) {
                float nvr = fmaf(v.x, r8.x, -v.y * r8.y);
                float nvi = fmaf(v.x, r8.y,  v.y * r8.x);
                v = make_float2(nvr, nvi);
            }
        R8S[(k - 1) * 32 + d] = v;
    }
    __syncthreads();

    // ---- fused table sweep: IjH + E1h (both perm16-packed); d = tid>>3 ----
    {
        int d  = tid >> 3;
        int i0 = tid & 7;
        float2 w = swS[d];
        int ip = d & 7;
        int np = ((ip & 3) << 1) | (ip >> 2);
        int colb = ((2 * d) & ~15) + 2 * np;     // IjH packed col (invariant)
        float bRe = Inj32[i0 * IP32 + 2 * d];    // r^{i0+1} (invariant across it)
        float bIm = Inj32[i0 * IP32 + 2 * d + 1];
        #pragma unroll
        for (int it = 0; it < 8; it++) {
            int i = i0 + it * 8;
            float re, im;                        // r^{i+1} = R8S[it-1] * r^{i0+1}
            if (it == 0) {
                re = bRe; im = bIm;
            } else {
                float2 A = R8S[(it - 1) * 32 + d];
                re = fmaf(A.x, bRe, -A.y * bIm);
                im = fmaf(A.x, bIm,  A.y * bRe);
            }
            *(uint32_t*)(IjH + i * EPH + colb) = packh2(re, -im);
            if (i < 63) {
                int col = perm16(62 - i);
                E1h[(2 * d) * EPH + col]     = __float2half_rn(fmaf(w.x, re, -w.y * im));
                E1h[(2 * d + 1) * EPH + col] = __float2half_rn(fmaf(w.x, im,  w.y * re));
            } else {
                int col = perm16(63);            // m=63 -> r^0 = 1
                E1h[(2 * d) * EPH + col]     = __float2half_rn(w.x);
                E1h[(2 * d + 1) * EPH + col] = __float2half_rn(w.y);
                r64S[d] = make_float2(re, im);   // r^64
            }
        }
    }
    __syncthreads();

    // ---- f[j] from IjH -> Gt direct (4 threads per j, shfl reduce) ----
    {
        int j = tid >> 2, dg = tid & 3;
        float s = 0.0f;
        #pragma unroll
        for (int dd = 0; dd < 8; dd++) {
            int d = dg * 8 + dd;
            float2 w = swS[d];
            float ijE, ijO;                      // (Re r^j, -Im r^j)
            if (j == 0) { ijE = 1.0f; ijO = 0.0f; }
            else {
                int ip = d & 7;
                int np = ((ip & 3) << 1) | (ip >> 2);
                int colb = ((2 * d) & ~15) + 2 * np;
                ijE = __half2float(IjH[(j - 1) * EPH + colb]);
                ijO = __half2float(IjH[(j - 1) * EPH + colb + 1]);
            }
            s = fmaf(w.x, ijE, fmaf(w.y, ijO, s));
        }
        s += __shfl_xor_sync(0xFFFFFFFFu, s, 1);
        s += __shfl_xor_sync(0xFFFFFFFFu, s, 2);
        if (dg == 0) {
            __half* Gt2 = (__half*)Gt32;
            __half hs = __float2half_rn(s);
            int p0 = j & 1, q0 = (j + 64 - p0) >> 1;   // f0 slot: t = j
            Gt2[(p0 * 64 + q0) * 2] = hs;
            if (j < 63) {                               // f1 slot: t = j+1
                int tt = j + 1;
                int p1 = tt & 1, q1 = (tt + 64 - p1) >> 1;
                Gt2[(p1 * 64 + q1) * 2 + 1] = hs;
            }
        }
    }

    int bn8 = lane >> 2, bl3 = lane & 3;
    uint32_t aoff = (uint32_t)(mw * 32 + (lane & 7) + ((lane >> 3) & 1) * 8)
                    * (PHH * 2) + ((lane >> 4) & 1) * 16;

    // ---- P GEMM: P[row][dt] = sum_m U[row][m] * E1[dt][m], K=64 ----
    {
        float pc[2][4][4];
        #pragma unroll
        for (int mt = 0; mt < 2; mt++)
            #pragma unroll
            for (int j = 0; j < 4; j++)
                #pragma unroll
                for (int q = 0; q < 4; q++) pc[mt][j][q] = 0.0f;

        #pragma unroll
        for (int ks = 0; ks < 4; ks++) {
            uint32_t a[2][4];
            ldmA(a[0], sb + UH_OFF + aoff + ks * 32);
            ldmA(a[1], sb + UH_OFF + aoff + 16 * (PHH * 2) + ks * 32);
            #pragma unroll
            for (int j = 0; j < 4; j++) {
                int tn = 2 * j + nw;
                uint2 bb = *(const uint2*)
                    (E1h + (tn * 8 + bn8) * EPH + ks * 16 + 4 * bl3);
                mma16(pc[0][j], a[0], bb.x, bb.y);
                mma16(pc[1][j], a[1], bb.x, bb.y);
            }
        }
        __syncthreads();   // CH overlay (Inj32/R8S) reads done -> CH writes safe
        #pragma unroll
        for (int mt = 0; mt < 2; mt++)
            #pragma unroll
            for (int j = 0; j < 4; j++) {
                int tn = 2 * j + nw;
                int ra  = mw * 32 + mt * 16 + bn8;
                int col = tn * 8 + 2 * bl3;
                *(uint32_t*)(CH + ra * PHH + col)       = packh2(pc[mt][j][0], pc[mt][j][1]);
                *(uint32_t*)(CH + (ra + 8) * PHH + col) = packh2(pc[mt][j][2], pc[mt][j][3]);
            }
    }
    __syncthreads();

    // ---- carry scan in CH ----
    {
        int tt = tid >> 6, seq = tid & 63;
        int bl = seq >> 5, d = seq & 31;
        float2 rl = r64S[d];
        float2 R = rl;                           // rl^16
        #pragma unroll
        for (int sq = 0; sq < 4; sq++) {
            float2 nR;
            nR.x = fmaf(R.x, R.x, -R.y * R.y);
            nR.y = 2.0f * R.x * R.y;
            R = nR;
        }
        __half* bp = CH + (bl * 64 + tt * 16) * PHH + 2 * d;
        float2 s = make_float2(0.0f, 0.0f);
        #pragma unroll
        for (int i = 0; i < 16; i++)
            s = cmad(rl, s, __half22float2(*(__half2*)(bp + i * PHH)));
        Sbuf[tt][seq] = s;
        __syncthreads();
        float2 X = c0S[d];
        for (int k = 0; k < tt; k++)             // tt uniform per warp
            X = cmad(R, X, Sbuf[k][seq]);
        #pragma unroll
        for (int i = 0; i < 16; i++) {
            float2 pv = __half22float2(*(__half2*)(bp + i * PHH));
            *(__half2*)(bp + i * PHH) = __floats2half2_rn(X.x, X.y);
            X = cmad(rl, X, pv);
        }
    }
    __syncthreads();

    // ---- Y GEMM ----
    float yc[2][4][4];
    #pragma unroll
    for (int mt = 0; mt < 2; mt++)
        #pragma unroll
        for (int j = 0; j < 4; j++)
            #pragma unroll
            for (int q = 0; q < 4; q++) yc[mt][j][q] = 0.0f;

    // half 2: u x Toeplitz(f), triangle-skip
    #pragma unroll
    for (int ks = 0; ks < 4; ks++) {
        uint32_t a[2][4];
        ldmA(a[0], sb + UH_OFF + aoff + ks * 32);
        ldmA(a[1], sb + UH_OFF + aoff + 16 * (PHH * 2) + ks * 32);
        #pragma unroll
        for (int j = 0; j < 4; j++) {
            int tn = 2 * j + nw;
            if (tn * 8 + 7 >= ks * 16) {
                int t0 = tn * 8 + bn8 - ks * 16 - 2 * bl3;
                int p  = t0 & 1;
                int q0 = (t0 + 64) >> 1;
                uint32_t b0 = Gt32[p * 64 + q0];
                uint32_t b1 = Gt32[p * 64 + q0 - 4];
                mma16(yc[0][j], a[0], b0, b1);
                mma16(yc[1][j], a[1], b0, b1);
            }
        }
    }
    // half 1: carries x injection
    #pragma unroll
    for (int ks = 0; ks < 4; ks++) {
        uint32_t a[2][4];
        ldmA(a[0], sb + CH_OFF + aoff + ks * 32);
        ldmA(a[1], sb + CH_OFF + aoff + 16 * (PHH * 2) + ks * 32);
        #pragma unroll
        for (int j = 0; j < 4; j++) {
            int tn = 2 * j + nw;
            uint2 bb = *(const uint2*)
                (IjH + (tn * 8 + bn8) * EPH + ks * 16 + 4 * bl3);
            mma16(yc[0][j], a[0], bb.x, bb.y);
            mma16(yc[1][j], a[1], bb.x, bb.y);
        }
    }

    // ---- epilogue: y = Y + D*u (u re-read from global, exact fp32) ----
    #pragma unroll
    for (int mt = 0; mt < 2; mt++)
        #pragma unroll
        for (int half = 0; half < 2; half++) {
            int r = mw * 32 + mt * 16 + bn8 + half * 8;
            size_t base = ((size_t)((b0 + (r >> 6)) * NH + h)) * NL + (r & 63) * 64;
            const float* up = u + base;
            float* op = out + base;
            #pragma unroll
            for (int j = 0; j < 4; j++) {
                int col = (2 * j + nw) * 8 + 2 * bl3;
                float2 uv = *(const float2*)(up + col);
                float2 o2;
                o2.x = fmaf(Dv, uv.x, yc[mt][j][half * 2 + 0]);
                o2.y = fmaf(Dv, uv.y, yc[mt][j][half * 2 + 1]);
                *(float2*)(op + col) = o2;
            }
        }
}

// ---------------------------------------------------------------------------
extern "C" void kernel_launch(void* const* d_in, const int* in_sizes, int n_in,
                              void* d_out, int out_size) {
    (void)in_sizes; (void)n_in; (void)out_size;
    const float* u     = (const float*)d_in[0];
    const float* theta = (const float*)d_in[1];
    const float* a     = (const float*)d_in[2];
    const float* Dp    = (const float*)d_in[3];
    const float* b_p   = (const float*)d_in[4];
    const float* c_p   = (const float*)d_in[5];
    const float* x0    = (const float*)d_in[6];
    float* out = (float*)d_out;

    cudaFuncSetAttribute(k_fused, cudaFuncAttributeMaxDynamicSharedMemorySize, SMEMF);
    k_fused<<<1024, 256, SMEMF>>>(u, theta, a, Dp, b_p, c_p, x0, out);
}

// round 16
// speedup vs baseline: 1.1383x; 1.1301x over previous
#include <cuda_runtime.h>
#include <cuda_fp16.h>
#include <cstdint>

#define NH 256
#define NL 4096
#define PHH 72     // Uh/CH pitch in halves (144B = 4 banks mod 32: ldmatrix conflict-free)
#define EPH 80     // E1h/IjH pitch in halves (160B = 8 banks mod 32: LDS.64 B-frags conflict-free)
#define IP32 66    // Inj32 pitch in floats (8 rows only)
#define UH_OFF  0
#define IJH_OFF 18432
#define E1_OFF  28672
#define CH_OFF  38912
#define SMEMF   57344      // 3 CTAs x 57344 = 172032 <= 228KB carveout

static __device__ __forceinline__ uint32_t s2u(const void* p) {
    uint32_t a;
    asm("{ .reg .u64 t; cvta.to.shared.u64 t, %1; cvt.u32.u64 %0, t; }" : "=r"(a) : "l"(p));
    return a;
}
static __device__ __forceinline__ void ldmA(uint32_t* a, uint32_t addr) {
    asm volatile("ldmatrix.sync.aligned.m8n8.x4.shared.b16 {%0,%1,%2,%3}, [%4];"
                 : "=r"(a[0]), "=r"(a[1]), "=r"(a[2]), "=r"(a[3]) : "r"(addr));
}
static __device__ __forceinline__ void mma16(float* c, const uint32_t* a,
                                             uint32_t b0, uint32_t b1) {
    asm volatile(
        "mma.sync.aligned.m16n8k16.row.col.f32.f16.f16.f32 "
        "{%0,%1,%2,%3},{%4,%5,%6,%7},{%8,%9},{%0,%1,%2,%3};"
        : "+f"(c[0]), "+f"(c[1]), "+f"(c[2]), "+f"(c[3])
        : "r"(a[0]), "r"(a[1]), "r"(a[2]), "r"(a[3]), "r"(b0), "r"(b1));
}
static __device__ __forceinline__ float2 cmad(float2 m, float2 c, float2 p) {
    float2 r;
    r.x = fmaf(m.x, c.x, fmaf(-m.y, c.y, p.x));
    r.y = fmaf(m.x, c.y, fmaf( m.y, c.x, p.y));
    return r;
}
static __device__ __forceinline__ uint32_t packh2(float a, float b) {
    __half2 h = __floats2half2_rn(a, b);
    return *(uint32_t*)&h;
}
// pair-permute within 16-half k-groups so B-frag (k-pair p, p+4) is one LDS.64
static __device__ __forceinline__ int perm16(int m) {
    int p = (m >> 1) & 7;
    int np = ((p & 3) << 1) | (p >> 2);
    return (m & ~15) | (np << 1) | (m & 1);
}

// ---------------------------------------------------------------------------
// Single-tile fused kernel. CTA = (h, b-pair), M=128, 256 threads, grid 1024.
// Dyn SMEM: Uh[128][72]h | IjH[64][80]h | E1h[64][80]h | CH[128][72]h
//           (Inj32[8][66]f + R8S[8][32]f2 overlay CH during table build)
// ---------------------------------------------------------------------------
__global__ __launch_bounds__(256, 3) void k_fused(
        const float* __restrict__ u,     const float* __restrict__ theta,
        const float* __restrict__ av_,   const float* __restrict__ Dp,
        const float* __restrict__ b_p,   const float* __restrict__ c_p,
        const float* __restrict__ x0,    float* __restrict__ out) {
    extern __shared__ char smc[];
    __half* Uh    = (__half*)(smc + UH_OFF);
    __half* IjH   = (__half*)(smc + IJH_OFF);
    __half* E1h   = (__half*)(smc + E1_OFF);
    __half* CH    = (__half*)(smc + CH_OFF);
    float*  Inj32 = (float*)(smc + CH_OFF);          // overlay (rows 0..7)
    float2* R8S   = (float2*)(smc + CH_OFF + 2112);  // overlay, [8][32]
    __shared__ float2 swS[32];
    __shared__ float2 c0S[32];
    __shared__ float2 r64S[32];
    __shared__ uint32_t Gt32[128];      // half2(f[t], f[t-1]), t = 2q + p - 64
    __shared__ float2 Sbuf[4][64];

    int tid  = threadIdx.x;
    int lane = tid & 31, warp = tid >> 5;
    int mw = warp & 3, nw = warp >> 2;          // 4(M) x 2(N) warp grid
    int h = blockIdx.x >> 2, b0 = (blockIdx.x & 3) * 2;
    const float T = 1.0f / (float)(NL - 1);
    float Dv = __ldg(&Dp[h]);
    uint32_t sb = s2u(smc);

    if (tid < 128) Gt32[tid] = 0u;              // zero-pad (ordered by later syncs)

    // ---- phase 0: u load + fp16 convert ----
    #pragma unroll
    for (int it = 0; it < 8; it++) {
        int idx = it * 256 + tid;
        int row = idx >> 4, c4 = (idx & 15) << 2;
        const float* src = u + ((size_t)((b0 + (row >> 6)) * NH + h)) * NL
                             + (row & 63) * 64 + c4;
        float4 v = *(const float4*)src;
        uint2 pk;
        pk.x = packh2(v.x, v.y);
        pk.y = packh2(v.z, v.w);
        *(uint2*)(Uh + row * PHH + c4) = pk;
    }

    // ---- phase A pass 1: r^p for p=1..8 (256 threads, MUFU), warp 0 sw/c0 ----
    {
        int p = (tid >> 5) + 1;                  // 1..8
        int d = tid & 31;
        int idx = h * 32 + d;
        float av = fabsf(av_[idx]);
        float th = theta[idx];
        float er = __expf(-av * T * (float)p);
        float sn, cn;
        __sincosf(th * T * (float)p, &sn, &cn);
        float rr = er * cn, ri = er * sn;
        Inj32[(p - 1) * IP32 + 2 * d]     = rr;
        Inj32[(p - 1) * IP32 + 2 * d + 1] = ri;
        if (p == 1) {                            // warp 0: uses own rr/ri = r^1
            float den = av * av + th * th;
            float nr = rr - 1.0f, ni = ri;
            float t0r = (nr * -av + ni * th) / den;
            float t0i = (ni * -av - nr * th) / den;
            float q = b_p[idx] * c_p[idx];
            swS[d] = make_float2(2.0f * t0r * q, 2.0f * t0i * q);
            float g = 4.0f * T * c_p[idx] * x0[idx];
            float rm2 = rr * rr + ri * ri;
            c0S[d] = make_float2(g * rr / rm2, -g * ri / rm2);
        }
    }
    __syncthreads();

    // ---- phase A pass 2: R8S[k-1][d] = (r^8)^k, k=1..8 (<=7 predicated cmuls) ----
    {
        int k = (tid >> 5) + 1;
        int d = tid & 31;
        float2 r8 = *(float2*)&Inj32[7 * IP32 + 2 * d];
        float2 v = r8;
        #pragma unroll
        for (int kk = 1; kk < 8; kk++)
            if (kk < k) {
                float nvr = fmaf(v.x, r8.x, -v.y * r8.y);
                float nvi = fmaf(v.x, r8.y,  v.y * r8.x);
                v = make_float2(nvr, nvi);
            }
        R8S[(k - 1) * 32 + d] = v;
    }
    __syncthreads();

    // ---- fused table sweep: IjH + E1h (both perm16-packed); d = tid>>3 ----
    {
        int d  = tid >> 3;
        int i0 = tid & 7;
        float2 w = swS[d];
        int ip = d & 7;
        int np = ((ip & 3) << 1) | (ip >> 2);
        int colb = ((2 * d) & ~15) + 2 * np;     // IjH packed col (invariant)
        float bRe = Inj32[i0 * IP32 + 2 * d];    // r^{i0+1} (invariant across it)
        float bIm = Inj32[i0 * IP32 + 2 * d + 1];
        #pragma unroll
        for (int it = 0; it < 8; it++) {
            int i = i0 + it * 8;
            float re, im;                        // r^{i+1} = R8S[it-1] * r^{i0+1}
            if (it == 0) {
                re = bRe; im = bIm;
            } else {
                float2 A = R8S[(it - 1) * 32 + d];
                re = fmaf(A.x, bRe, -A.y * bIm);
                im = fmaf(A.x, bIm,  A.y * bRe);
            }
            *(uint32_t*)(IjH + i * EPH + colb) = packh2(re, -im);
            if (i < 63) {
                int col = perm16(62 - i);
                E1h[(2 * d) * EPH + col]     = __float2half_rn(fmaf(w.x, re, -w.y * im));
                E1h[(2 * d + 1) * EPH + col] = __float2half_rn(fmaf(w.x, im,  w.y * re));
            } else {
                int col = perm16(63);            // m=63 -> r^0 = 1
                E1h[(2 * d) * EPH + col]     = __float2half_rn(w.x);
                E1h[(2 * d + 1) * EPH + col] = __float2half_rn(w.y);
                r64S[d] = make_float2(re, im);   // r^64
            }
        }
    }
    __syncthreads();

    // ---- f[j] from IjH -> Gt direct (4 threads per j, shfl reduce) ----
    {
        int j = tid >> 2, dg = tid & 3;
        float s = 0.0f;
        #pragma unroll
        for (int dd = 0; dd < 8; dd++) {
            int d = dg * 8 + dd;
            float2 w = swS[d];
            float ijE, ijO;                      // (Re r^j, -Im r^j)
            if (j == 0) { ijE = 1.0f; ijO = 0.0f; }
            else {
                int ip = d & 7;
                int np = ((ip & 3) << 1) | (ip >> 2);
                int colb = ((2 * d) & ~15) + 2 * np;
                uint32_t ij = *(const uint32_t*)(IjH + (j - 1) * EPH + colb);
                __half2 hij = *(__half2*)&ij;
                ijE = __low2float(hij);
                ijO = __high2float(hij);
            }
            s = fmaf(w.x, ijE, fmaf(w.y, ijO, s));
        }
        s += __shfl_xor_sync(0xFFFFFFFFu, s, 1);
        s += __shfl_xor_sync(0xFFFFFFFFu, s, 2);
        if (dg == 0) {
            __half* Gt2 = (__half*)Gt32;
            __half hs = __float2half_rn(s);
            int p0 = j & 1, q0 = (j + 64 - p0) >> 1;   // f0 slot: t = j
            Gt2[(p0 * 64 + q0) * 2] = hs;
            if (j < 63) {                               // f1 slot: t = j+1
                int tt = j + 1;
                int p1 = tt & 1, q1 = (tt + 64 - p1) >> 1;
                Gt2[(p1 * 64 + q1) * 2 + 1] = hs;
            }
        }
    }

    int bn8 = lane >> 2, bl3 = lane & 3;
    uint32_t aoff = (uint32_t)(mw * 32 + (lane & 7) + ((lane >> 3) & 1) * 8)
                    * (PHH * 2) + ((lane >> 4) & 1) * 16;

    // ---- P GEMM: P[row][dt] = sum_m U[row][m] * E1[dt][m], K=64 ----
    {
        float pc[2][4][4];
        #pragma unroll
        for (int mt = 0; mt < 2; mt++)
            #pragma unroll
            for (int j = 0; j < 4; j++)
                #pragma unroll
                for (int q = 0; q < 4; q++) pc[mt][j][q] = 0.0f;

        #pragma unroll
        for (int ks = 0; ks < 4; ks++) {
            uint32_t a[2][4];
            ldmA(a[0], sb + UH_OFF + aoff + ks * 32);
            ldmA(a[1], sb + UH_OFF + aoff + 16 * (PHH * 2) + ks * 32);
            #pragma unroll
            for (int j = 0; j < 4; j++) {
                int tn = 2 * j + nw;
                uint2 bb = *(const uint2*)
                    (E1h + (tn * 8 + bn8) * EPH + ks * 16 + 4 * bl3);
                mma16(pc[0][j], a[0], bb.x, bb.y);
                mma16(pc[1][j], a[1], bb.x, bb.y);
            }
        }
        __syncthreads();   // CH overlay (Inj32/R8S) reads done -> CH writes safe
        #pragma unroll
        for (int mt = 0; mt < 2; mt++)
            #pragma unroll
            for (int j = 0; j < 4; j++) {
                int tn = 2 * j + nw;
                int ra  = mw * 32 + mt * 16 + bn8;
                int col = tn * 8 + 2 * bl3;
                *(uint32_t*)(CH + ra * PHH + col)       = packh2(pc[mt][j][0], pc[mt][j][1]);
                *(uint32_t*)(CH + (ra + 8) * PHH + col) = packh2(pc[mt][j][2], pc[mt][j][3]);
            }
    }
    __syncthreads();

    // ---- carry scan in CH ----
    {
        int tt = tid >> 6, seq = tid & 63;
        int bl = seq >> 5, d = seq & 31;
        float2 rl = r64S[d];
        float2 R = rl;                           // rl^16
        #pragma unroll
        for (int sq = 0; sq < 4; sq++) {
            float2 nR;
            nR.x = fmaf(R.x, R.x, -R.y * R.y);
            nR.y = 2.0f * R.x * R.y;
            R = nR;
        }
        __half* bp = CH + (bl * 64 + tt * 16) * PHH + 2 * d;
        float2 s = make_float2(0.0f, 0.0f);
        #pragma unroll
        for (int i = 0; i < 16; i++)
            s = cmad(rl, s, __half22float2(*(__half2*)(bp + i * PHH)));
        Sbuf[tt][seq] = s;
        __syncthreads();
        float2 X = c0S[d];
        for (int k = 0; k < tt; k++)             // tt uniform per warp
            X = cmad(R, X, Sbuf[k][seq]);
        #pragma unroll
        for (int i = 0; i < 16; i++) {
            float2 pv = __half22float2(*(__half2*)(bp + i * PHH));
            *(__half2*)(bp + i * PHH) = __floats2half2_rn(X.x, X.y);
            X = cmad(rl, X, pv);
        }
    }
    __syncthreads();

    // ---- Y GEMM ----
    float yc[2][4][4];
    #pragma unroll
    for (int mt = 0; mt < 2; mt++)
        #pragma unroll
        for (int j = 0; j < 4; j++)
            #pragma unroll
            for (int q = 0; q < 4; q++) yc[mt][j][q] = 0.0f;

    // half 2: u x Toeplitz(f), triangle-skip
    #pragma unroll
    for (int ks = 0; ks < 4; ks++) {
        uint32_t a[2][4];
        ldmA(a[0], sb + UH_OFF + aoff + ks * 32);
        ldmA(a[1], sb + UH_OFF + aoff + 16 * (PHH * 2) + ks * 32);
        #pragma unroll
        for (int j = 0; j < 4; j++) {
            int tn = 2 * j + nw;
            if (tn * 8 + 7 >= ks * 16) {
                int t0 = tn * 8 + bn8 - ks * 16 - 2 * bl3;
                int p  = t0 & 1;
                int q0 = (t0 + 64) >> 1;
                uint32_t b0 = Gt32[p * 64 + q0];
                uint32_t b1 = Gt32[p * 64 + q0 - 4];
                mma16(yc[0][j], a[0], b0, b1);
                mma16(yc[1][j], a[1], b0, b1);
            }
        }
    }
    // half 1: carries x injection
    #pragma unroll
    for (int ks = 0; ks < 4; ks++) {
        uint32_t a[2][4];
        ldmA(a[0], sb + CH_OFF + aoff + ks * 32);
        ldmA(a[1], sb + CH_OFF + aoff + 16 * (PHH * 2) + ks * 32);
        #pragma unroll
        for (int j = 0; j < 4; j++) {
            int tn = 2 * j + nw;
            uint2 bb = *(const uint2*)
                (IjH + (tn * 8 + bn8) * EPH + ks * 16 + 4 * bl3);
            mma16(yc[0][j], a[0], bb.x, bb.y);
            mma16(yc[1][j], a[1], bb.x, bb.y);
        }
    }

    // ---- epilogue: y = Y + D*u (u re-read from global, exact fp32) ----
    #pragma unroll
    for (int mt = 0; mt < 2; mt++)
        #pragma unroll
        for (int half = 0; half < 2; half++) {
            int r = mw * 32 + mt * 16 + bn8 + half * 8;
            size_t base = ((size_t)((b0 + (r >> 6)) * NH + h)) * NL + (r & 63) * 64;
            const float* up = u + base;
            float* op = out + base;
            #pragma unroll
            for (int j = 0; j < 4; j++) {
                int col = (2 * j + nw) * 8 + 2 * bl3;
                float2 uv = *(const float2*)(up + col);
                float2 o2;
                o2.x = fmaf(Dv, uv.x, yc[mt][j][half * 2 + 0]);
                o2.y = fmaf(Dv, uv.y, yc[mt][j][half * 2 + 1]);
                *(float2*)(op + col) = o2;
            }
        }
}

// ---------------------------------------------------------------------------
extern "C" void kernel_launch(void* const* d_in, const int* in_sizes, int n_in,
                              void* d_out, int out_size) {
    (void)in_sizes; (void)n_in; (void)out_size;
    const float* u     = (const float*)d_in[0];
    const float* theta = (const float*)d_in[1];
    const float* a     = (const float*)d_in[2];
    const float* Dp    = (const float*)d_in[3];
    const float* b_p   = (const float*)d_in[4];
    const float* c_p   = (const float*)d_in[5];
    const float* x0    = (const float*)d_in[6];
    float* out = (float*)d_out;

    cudaFuncSetAttribute(k_fused, cudaFuncAttributeMaxDynamicSharedMemorySize, SMEMF);
    k_fused<<<1024, 256, SMEMF>>>(u, theta, a, Dp, b_p, c_p, x0, out);
}